// round 1
// baseline (speedup 1.0000x reference)
#include <cuda_runtime.h>
#include <stdint.h>

#define NSTEP 1000
#define NELEM 45056     // 16*1*64*44
#define HW    2816      // 64*44
#define PF    8         // noise prefetch depth in solve kernel

// Scratch (static device globals; no dynamic allocation allowed)
__device__ uint32_t g_keys[NSTEP * 2];
__device__ float4   g_stepc[NSTEP];                 // {P, Q, c1, temb}
__device__ float    g_noise[(NSTEP + PF) * NELEM];  // padded for prefetch

// ---------------- Threefry-2x32 (exact JAX rounds/rotations) ----------------
__device__ __forceinline__ void tf_round(uint32_t& x0, uint32_t& x1, int r) {
  x0 += x1;
  x1 = __funnelshift_l(x1, x1, r);  // rotl
  x1 ^= x0;
}

__device__ __forceinline__ void threefry2x32(uint32_t ks0, uint32_t ks1,
                                             uint32_t x0, uint32_t x1,
                                             uint32_t& o0, uint32_t& o1) {
  const uint32_t ks2 = ks0 ^ ks1 ^ 0x1BD11BDAu;
  x0 += ks0; x1 += ks1;
  tf_round(x0, x1, 13); tf_round(x0, x1, 15); tf_round(x0, x1, 26); tf_round(x0, x1, 6);
  x0 += ks1; x1 += ks2 + 1u;
  tf_round(x0, x1, 17); tf_round(x0, x1, 29); tf_round(x0, x1, 16); tf_round(x0, x1, 24);
  x0 += ks2; x1 += ks0 + 2u;
  tf_round(x0, x1, 13); tf_round(x0, x1, 15); tf_round(x0, x1, 26); tf_round(x0, x1, 6);
  x0 += ks0; x1 += ks1 + 3u;
  tf_round(x0, x1, 17); tf_round(x0, x1, 29); tf_round(x0, x1, 16); tf_round(x0, x1, 24);
  x0 += ks1; x1 += ks2 + 4u;
  tf_round(x0, x1, 13); tf_round(x0, x1, 15); tf_round(x0, x1, 26); tf_round(x0, x1, 6);
  o0 = x0 + ks2;
  o1 = x1 + ks0 + 5u;
}

// -------- bits -> N(0,1): JAX uniform(lo=-0.99999994, hi=1) + sqrt2*erfinv --------
__device__ __forceinline__ float bits_to_normal(uint32_t bits) {
  float f = __uint_as_float((bits >> 9) | 0x3f800000u) - 1.0f;  // [0,1)
  float u = fmaf(f, 2.0f, -0.99999994f);                        // (hi-lo) rounds to 2.0f
  float w = -__logf(fmaf(-u, u, 1.0f));
  float p;
  if (w < 5.0f) {  // XLA ErfInv32 coefficients (Giles)
    w -= 2.5f;
    p =             2.81022636e-08f;
    p = fmaf(p, w,  3.43273939e-07f);
    p = fmaf(p, w, -3.5233877e-06f);
    p = fmaf(p, w, -4.39150654e-06f);
    p = fmaf(p, w,  0.00021858087f);
    p = fmaf(p, w, -0.00125372503f);
    p = fmaf(p, w, -0.00417768164f);
    p = fmaf(p, w,  0.246640727f);
    p = fmaf(p, w,  1.50140941f);
  } else {
    w = sqrtf(w) - 3.0f;
    p =            -0.000200214257f;
    p = fmaf(p, w,  0.000100950558f);
    p = fmaf(p, w,  0.00134934322f);
    p = fmaf(p, w, -0.00367342844f);
    p = fmaf(p, w,  0.00573950773f);
    p = fmaf(p, w, -0.0076224613f);
    p = fmaf(p, w,  0.00943887047f);
    p = fmaf(p, w,  1.00167406f);
    p = fmaf(p, w,  2.83297682f);
  }
  return 1.41421356f * (p * u);
}

// ---------------- Kernel 1: schedule + folded keys ----------------
__global__ void sched_kernel(const float* __restrict__ t_scale_p) {
  const int t = threadIdx.x;
  __shared__ double part[256];
  __shared__ float  alph[NSTEP + 1];

  const double bstep = (0.02 - 1e-4) / 999.0;
  double loc[4];
  double prod = 1.0;
  if (t < 250) {
#pragma unroll
    for (int j = 0; j < 4; j++) {
      int i = 4 * t + j;
      double beta = (i == 999) ? 0.02 : (1e-4 + (double)i * bstep);
      prod *= (1.0 - beta);
      loc[j] = prod;
    }
  }
  part[t] = prod;
  __syncthreads();
  // inclusive scan (product) over 256 chunk-products
  for (int off = 1; off < 256; off <<= 1) {
    double u = (t >= off) ? part[t - off] : 1.0;
    double v = part[t];
    __syncthreads();
    part[t] = u * v;
    __syncthreads();
  }
  double pre = (t == 0) ? 1.0 : part[t - 1];
  if (t == 0) alph[0] = 1.0f;
  if (t < 250) {
#pragma unroll
    for (int j = 0; j < 4; j++)
      alph[4 * t + j + 1] = (float)(pre * loc[j]);
  }
  __syncthreads();

  const float tsc = *t_scale_p;
  if (t < 250) {
    for (int j = 0; j < 4; j++) {
      int k = 4 * t + j;        // step index in reversed-time order
      int idx = 999 - k;
      float at  = alph[idx + 1];
      float atn = alph[idx];    // k==999 -> alph[0]=1
      float a1 = 1.0f - at / atn;
      float c1 = 0.1f * sqrtf(a1 * (1.0f - atn) / (1.0f - at));
      float c2 = sqrtf(fmaxf(1.0f - atn - c1 * c1, 0.0f));
      double s1 = sqrt(1.0 - (double)at);
      double Q  = (double)c2 / s1;                         // coeff of sil_T
      double P  = (double)sqrtf(atn) - Q * (double)sqrtf(at); // coeff of sil_0
      float temb = tsc * ((float)idx / 1000.0f);
      g_stepc[k] = make_float4((float)P, (float)Q, c1, temb);
      // folded key: threefry(key=(0,42), count=[0, idx])
      uint32_t k0, k1;
      threefry2x32(0u, 42u, 0u, (uint32_t)idx, k0, k1);
      g_keys[2 * k]     = k0;
      g_keys[2 * k + 1] = k1;
    }
  }
}

// ---------------- Kernel 2: noise generation (partitionable threefry) ----------------
// bits[i] = out0 ^ out1 of threefry2x32(key_step, hi32(i)=0, lo32(i)=i)
__global__ void __launch_bounds__(256) noise_kernel() {
  const int step = blockIdx.y;
  const uint32_t ks0 = g_keys[2 * step];
  const uint32_t ks1 = g_keys[2 * step + 1];
  float* out = g_noise + (size_t)step * NELEM;
  const int i0 = blockIdx.x * 256 + threadIdx.x;
#pragma unroll
  for (int j = 0; j < 8; j++) {
    const int i = i0 + j * 5632;  // 22 blocks * 256 threads
    uint32_t o0, o1;
    threefry2x32(ks0, ks1, 0u, (uint32_t)i, o0, o1);
    out[i] = bits_to_normal(o0 ^ o1);
  }
}

// ---------------- Kernel 3: sequential 1000-step solve ----------------
__global__ void __launch_bounds__(256) solve_kernel(
    const float* __restrict__ skes, const float* __restrict__ silT_g,
    const float* __restrict__ w_skes, const float* __restrict__ w_sil_p,
    float* __restrict__ preds) {
  __shared__ float4 sc[NSTEP];
  for (int j = threadIdx.x; j < NSTEP; j += 256) sc[j] = g_stepc[j];
  __syncthreads();

  const int i  = blockIdx.x * 256 + threadIdx.x;  // < 45056 exactly
  const int ns = i / HW;
  const int r  = i - ns * HW;
  const int n  = ns >> 3, s = ns & 7;
  const float* b = skes + (size_t)(n * 24 + s) * HW + r;  // (n,c,s,h,w), c stride = 8*HW
  const float cond = b[0] * w_skes[0] + b[8 * HW] * w_skes[1] + b[16 * HW] * w_skes[2];
  const float silT = silT_g[i];
  const float wsil = *w_sil_p;

  float sil = silT;
  float nz[PF];
  const float* ng = g_noise + i;
#pragma unroll
  for (int j = 0; j < PF; j++) nz[j] = ng[(size_t)j * NELEM];

  float* op = preds + i;
  for (int k = 0; k < NSTEP; k += PF) {
#pragma unroll
    for (int u = 0; u < PF; u++) {
      const float4 c = sc[k + u];
      const float z  = fmaf(wsil, sil, cond + c.w);
      const float s0 = tanhf(z);
      op[(size_t)(k + u) * NELEM] = s0;
      sil = fmaf(c.x, s0, fmaf(c.z, nz[u], c.y * silT));
      nz[u] = ng[(size_t)(k + u + PF) * NELEM];  // prefetch (padded past step 999)
    }
  }
}

// ---------------- Launch ----------------
extern "C" void kernel_launch(void* const* d_in, const int* in_sizes, int n_in,
                              void* d_out, int out_size) {
  const float* skes    = (const float*)d_in[0];  // (2,3,8,64,44)
  const float* sil_T   = (const float*)d_in[1];  // (16,1,64,44)
  const float* w_skes  = (const float*)d_in[2];  // (3,)
  const float* w_sil   = (const float*)d_in[3];  // ()
  const float* t_scale = (const float*)d_in[4];  // ()
  float* preds = (float*)d_out;                  // (1000,16,1,64,44)

  sched_kernel<<<1, 256>>>(t_scale);
  noise_kernel<<<dim3(22, NSTEP), 256>>>();
  solve_kernel<<<176, 256>>>(skes, sil_T, w_skes, w_sil, preds);
}